// round 14
// baseline (speedup 1.0000x reference)
#include <cuda_runtime.h>
#include <math.h>

#define BB 4
#define DD 96
#define HH 160
#define WW 160
#define HW (HH*WW)
#define NSCAL 28
#define NACC  78

// Global accumulators (double); zeroed by zero_kernel each launch.
__device__ double g_acc[BB][80];

typedef unsigned long long u64t;
__device__ __forceinline__ u64t pack2(float lo, float hi) {
    u64t r; asm("mov.b64 %0,{%1,%2};" : "=l"(r) : "f"(lo), "f"(hi)); return r;
}
__device__ __forceinline__ void unpack2(float& lo, float& hi, u64t v) {
    asm("mov.b64 {%0,%1},%2;" : "=f"(lo), "=f"(hi) : "l"(v));
}
__device__ __forceinline__ void fma2(u64t& d, u64t a, u64t b) {
    asm("fma.rn.f32x2 %0,%1,%2,%0;" : "+l"(d) : "l"(a), "l"(b));
}

__global__ void zero_kernel() {
    int i = threadIdx.x;
    if (i < BB * 80) ((double*)g_acc)[i] = 0.0;
}

// ============================================================
// Fused kernel. ONE barrier per z-plane: compute(z) reads raw
// slots {z&3,(z+1)&3} + aux slot z&1; stage(z) writes raw
// (z+2)&3 + aux (z+1)&1 — disjoint, so no pre-stage barrier
// is needed. FP64 only as F2F converts at block end.
// ============================================================
#define TXX 32
#define TYV 16            // voxel rows per tile
#define HR  (TYV + 2)     // 18 halo rows
#define HC  (TXX + 2)     // 34 halo cols
#define ANL (HR * HC)     // 612
#define ZCH 24
#define HPITCH 258        // u16 row pitch (256 threads + 2 pad)

__global__ __launch_bounds__(256, 3)
void fused_kernel(const float* __restrict__ X, const float* __restrict__ M,
                  const float* __restrict__ GF) {
    __shared__ float xsh[4][HR][HC];
    __shared__ float msk[4][HR][HC];
    __shared__ float2 aux[2][HR][HC];            // (t, s)
    __shared__ unsigned short h16[50 * HPITCH];  // per-thread histogram
    __shared__ float red[NSCAL][8];
    __shared__ float wsm[48];                    // w[8][5] + cf[8]

    const int tx = threadIdx.x, ty = threadIdx.y;     // ty in 0..7
    const int tid = ty * TXX + tx;
    const int warp = tid >> 5, lane = tid & 31;
    const int x0 = blockIdx.x * TXX, y0 = blockIdx.y * TYV;
    const int b = blockIdx.z >> 2;
    const int zs = (blockIdx.z & 3) * ZCH;
    const float* Xb = X + (size_t)b * DD * HW;
    const float* Mb = M + (size_t)b * DD * HW;
    const float A = 0.13533528323661270f;  // exp(-2)

    // zero per-thread histogram (u32 strided)
    {
        unsigned* h32 = (unsigned*)h16;
        #pragma unroll
        for (int i = tid; i < 50 * HPITCH / 2; i += 256) h32[i] = 0u;
    }

    // derive weights (threads 0..7, one filter each):
    // F[dz][j] = gz[dz]*u[j] - c, gz=[a,1,a] => u[j]=(F1-F0)/(1-a)
    // conv = sum_sym ubar_k * tsym_k - cf*box ; u symmetric (u[j]==u[8-j])
    if (tid < 8) {
        float u[9], cacc = 0.0f;
        #pragma unroll
        for (int j = 0; j < 9; j++) {
            float F1 = GF[tid * 27 + 9 + j];
            float F0 = GF[tid * 27 + j];
            u[j] = (F1 - F0) * (1.0f / (1.0f - A));
            cacc += (u[j] - F1);
        }
        wsm[40 + tid] = cacc * (1.0f / 9.0f);
        wsm[tid * 5 + 0] = (u[0] + u[8]) * 0.5f;
        wsm[tid * 5 + 1] = (u[1] + u[7]) * 0.5f;
        wsm[tid * 5 + 2] = (u[2] + u[6]) * 0.5f;
        wsm[tid * 5 + 3] = (u[3] + u[5]) * 0.5f;
        wsm[tid * 5 + 4] = u[4];
    }

    // halo-load slots (3 segments, z-invariant)
    int loff[3]; bool lval[3];
    #pragma unroll
    for (int s = 0; s < 3; s++) {
        int i = tid + s * 256;
        bool ok = (i < ANL);
        int ry = ok ? i / HC : 0, rx = ok ? i % HC : 0;
        int gy = y0 + ry - 1, gx = x0 + rx - 1;
        lval[s] = ok && gy >= 0 && gy < HH && gx >= 0 && gx < WW;
        loff[s] = gy * WW + gx;
    }

    float xmR[3], xcR[3];

    // preload raw planes zs (slot 0), zs+1 (slot 1); aux(zs) slot 0.
    // Plane zs-1 contributes to aux via registers only (not stored).
    #pragma unroll
    for (int s = 0; s < 3; s++) {
        int i = tid + s * 256;
        if (i < ANL) {
            float xv_m = 0, xv_0 = 0, mv_0 = 0, xv_p = 0, mv_p = 0;
            if (lval[s]) {
                if (zs > 0) xv_m = __ldg(Xb + (size_t)(zs - 1) * HW + loff[s]);
                xv_0 = __ldg(Xb + (size_t)zs * HW + loff[s]);
                mv_0 = __ldg(Mb + (size_t)zs * HW + loff[s]);
                xv_p = __ldg(Xb + (size_t)(zs + 1) * HW + loff[s]);
                mv_p = __ldg(Mb + (size_t)(zs + 1) * HW + loff[s]);
            }
            (&xsh[0][0][0])[i] = xv_0;  (&msk[0][0][0])[i] = mv_0;
            (&xsh[1][0][0])[i] = xv_p;  (&msk[1][0][0])[i] = mv_p;
            float mp2 = xv_m + xv_p;
            (&aux[0][0][0])[i] = make_float2(fmaf(A, mp2, xv_0), mp2 + xv_0);
            xmR[s] = xv_0;
            xcR[s] = xv_p;
        }
    }

    const u64t ABSM = 0x7FFFFFFF7FFFFFFFull;
    u64t gab2[4] = {0ull, 0ull, 0ull, 0ull};
    float n = 0, m1 = 0, m2 = 0, m3 = 0, m4 = 0;
    float lbp[6] = {0, 0, 0, 0, 0, 0};
    float gs[3] = {0, 0, 0}, gc[3] = {0, 0, 0}, gh[3] = {0, 0, 0};

    const int vy0 = 2 * ty + 1, vy1 = 2 * ty + 2, txc = tx + 1;

    // center-column x at zs-1 (direct LDG; slot-3 preload removed)
    float cd0 = 0.0f, cd1 = 0.0f;
    if (zs > 0) {
        cd0 = __ldg(Xb + (size_t)(zs - 1) * HW + (y0 + vy0 - 1) * WW + x0 + tx);
        cd1 = __ldg(Xb + (size_t)(zs - 1) * HW + (y0 + vy1 - 1) * WW + x0 + tx);
    }

    __syncthreads();   // hist zero + weights + preload visible

    // packed weights: pair filters (2p, 2p+1)
    u64t w2[20], cf2[4];
    #pragma unroll
    for (int p = 0; p < 4; p++) {
        #pragma unroll
        for (int k = 0; k < 5; k++)
            w2[p * 5 + k] = pack2(wsm[(2 * p) * 5 + k], wsm[(2 * p + 1) * 5 + k]);
        cf2[p] = pack2(-wsm[40 + 2 * p], -wsm[40 + 2 * p + 1]);
    }

    // center-column register rotation state (c, mc per voxel)
    float cc0 = xsh[0][vy0][txc], cc1 = xsh[0][vy1][txc];
    float cm0 = msk[0][vy0][txc], cm1 = msk[0][vy1][txc];

    for (int z = zs; z < zs + ZCH; z++) {
        // issue LDGs for plane z+2 early
        float xn[3] = {0, 0, 0}, mn[3] = {0, 0, 0};
        {
            int zq = z + 2;
            if (zq < DD) {
                const float* Px = Xb + (size_t)zq * HW;
                const float* Pm = Mb + (size_t)zq * HW;
                #pragma unroll
                for (int s = 0; s < 3; s++)
                    if (lval[s]) { xn[s] = __ldg(Px + loff[s]); mn[s] = __ldg(Pm + loff[s]); }
            }
        }

        const int q1 = z & 3, q2 = (z + 1) & 3, az = z & 1;

        // ---- aux window: 4 rows x 3 cols (12 LDS.64) covers both voxels ----
        float t[4][3], rowS[4];
        #pragma unroll
        for (int r = 0; r < 4; r++) {
            float2 a0 = aux[az][2 * ty + r][tx    ];
            float2 a1 = aux[az][2 * ty + r][tx + 1];
            float2 a2 = aux[az][2 * ty + r][tx + 2];
            t[r][0] = a0.x; t[r][1] = a1.x; t[r][2] = a2.x;
            rowS[r] = a0.y + a1.y + a2.y;
        }

        // ---- raw reads (split x / m); center column from registers ----
        float xv0 = xsh[q1][vy0 - 1][txc];
        float xv1 = cc0;
        float xv2 = cc1;
        float xv3 = xsh[q1][vy1 + 1][txc];
        float xxm0 = xsh[q1][vy0][tx], xxp0 = xsh[q1][vy0][tx + 2];
        float xxm1 = xsh[q1][vy1][tx], xxp1 = xsh[q1][vy1][tx + 2];
        float xup0 = xsh[q2][vy0][txc], xup1 = xsh[q2][vy1][txc];
        float xdn0 = cd0, xdn1 = cd1;
        float mc0 = cm0, mc1 = cm1;
        float myp1 = msk[q1][vy1 + 1][txc];
        float mxp0 = msk[q1][vy0][tx + 2], mxp1 = msk[q1][vy1][tx + 2];
        float mzp0 = msk[q2][vy0][txc], mzp1 = msk[q2][vy1][txc];

        #define DO_VOXEL(R, CC, MC, XUP, XDN, XYP, XYM, XXP, XXM, MZP, MYP, MXP)          \
        {                                                                                  \
            float C  = t[R][0] + t[R + 2][2];                                              \
            float CA = t[R][2] + t[R + 2][0];                                              \
            float Ey = t[R][1] + t[R + 2][1];                                              \
            float Ex = t[R + 1][0] + t[R + 1][2];                                          \
            float ct = t[R + 1][1];                                                        \
            float box = rowS[R] + rowS[R + 1] + rowS[R + 2];                               \
            u64t T0 = pack2(C, C),  T1 = pack2(Ey, Ey), T2 = pack2(CA, CA);                \
            u64t T3 = pack2(Ex, Ex), T4 = pack2(ct, ct), BX = pack2(box, box);             \
            u64t mcp = pack2(MC, MC);                                                      \
            _Pragma("unroll")                                                              \
            for (int p = 0; p < 4; p++) {                                                  \
                u64t acc = 0ull;                                                           \
                fma2(acc, w2[p * 5 + 0], T0);                                              \
                fma2(acc, w2[p * 5 + 1], T1);                                              \
                fma2(acc, w2[p * 5 + 2], T2);                                              \
                fma2(acc, w2[p * 5 + 3], T3);                                              \
                fma2(acc, w2[p * 5 + 4], T4);                                              \
                fma2(acc, cf2[p], BX);                                                     \
                acc &= ABSM;                                                               \
                fma2(gab2[p], acc, mcp);                                                   \
            }                                                                              \
            float c2 = CC * CC;                                                            \
            n += MC;                                                                       \
            m1 = fmaf(MC, CC, m1);                                                         \
            m2 = fmaf(MC, c2, m2);                                                         \
            float mcc = MC * CC;                                                           \
            m3 = fmaf(mcc, c2, m3);                                                        \
            m4 = fmaf(MC * c2, c2, m4);                                                    \
            if (MC > 0.5f && CC >= -1.0f && CC <= 1.0f) {                                  \
                int bi = (int)floorf(__fmul_rn(__fadd_rn(CC, 1.0f), 25.0f));               \
                bi = min(max(bi, 0), 49);                                                  \
                h16[bi * HPITCH + tid] += 1;                                               \
            }                                                                              \
            bool mb = MC > 0.5f;                                                           \
            if (mb) {                                                                      \
                lbp[0] += (CC - XUP > 0.0f) ? 1.0f : 0.0f;                                 \
                lbp[1] += (CC - XDN > 0.0f) ? 1.0f : 0.0f;                                 \
                lbp[2] += (CC - XYP > 0.0f) ? 1.0f : 0.0f;                                 \
                lbp[3] += (CC - XYM > 0.0f) ? 1.0f : 0.0f;                                 \
                lbp[4] += (CC - XXP > 0.0f) ? 1.0f : 0.0f;                                 \
                lbp[5] += (CC - XXM > 0.0f) ? 1.0f : 0.0f;                                 \
            }                                                                              \
            {                                                                              \
                float mp = (mb && MZP > 0.5f) ? 1.0f : 0.0f;                               \
                float d = CC - XUP, dd = d * d;                                            \
                gs[0] += mp;                                                               \
                gc[0] = fmaf(mp, dd, gc[0]);                                               \
                gh[0] = fmaf(mp, __fdividef(1.0f, 1.0f + dd), gh[0]);                      \
            }                                                                              \
            {                                                                              \
                float mp = (mb && MYP > 0.5f) ? 1.0f : 0.0f;                               \
                float d = CC - XYP, dd = d * d;                                            \
                gs[1] += mp;                                                               \
                gc[1] = fmaf(mp, dd, gc[1]);                                               \
                gh[1] = fmaf(mp, __fdividef(1.0f, 1.0f + dd), gh[1]);                      \
            }                                                                              \
            {                                                                              \
                float mp = (mb && MXP > 0.5f) ? 1.0f : 0.0f;                               \
                float d = CC - XXP, dd = d * d;                                            \
                gs[2] += mp;                                                               \
                gc[2] = fmaf(mp, dd, gc[2]);                                               \
                gh[2] = fmaf(mp, __fdividef(1.0f, 1.0f + dd), gh[2]);                      \
            }                                                                              \
        }

        DO_VOXEL(0, xv1, mc0, xup0, xdn0, xv2, xv0, xxp0, xxm0, mzp0, mc1,  mxp0)
        DO_VOXEL(1, xv2, mc1, xup1, xdn1, xv3, xv1, xxp1, xxm1, mzp1, myp1, mxp1)
        #undef DO_VOXEL

        // rotate center-column registers
        cd0 = cc0; cd1 = cc1;
        cc0 = xup0; cc1 = xup1;
        cm0 = mzp0; cm1 = mzp1;

        // ---- stage: aux(z+1) from register history; raw(z+2).
        // Write slots {(z+2)&3, (z+1)&1} are disjoint from this
        // iteration's read slots {z&3,(z+1)&3, z&1} -> no barrier
        // needed before staging.
        {
            int swq = (z + 2) & 3, swa = (z + 1) & 1;
            float* bx = &xsh[swq][0][0];
            float* bm = &msk[swq][0][0];
            float2* ba = &aux[swa][0][0];
            #pragma unroll
            for (int s = 0; s < 3; s++) {
                int i = tid + s * 256;
                if (s < 2 || i < ANL) {
                    float mp2 = xmR[s] + xn[s];
                    ba[i] = make_float2(fmaf(A, mp2, xcR[s]), mp2 + xcR[s]);
                    bx[i] = xn[s];
                    bm[i] = mn[s];
                    xmR[s] = xcR[s]; xcR[s] = xn[s];
                }
            }
        }
        __syncthreads();   // staging visible before next-plane reads
    }

    // ---- block reduction of 28 scalars ----
    float gabf[8];
    unpack2(gabf[0], gabf[1], gab2[0]);
    unpack2(gabf[2], gabf[3], gab2[1]);
    unpack2(gabf[4], gabf[5], gab2[2]);
    unpack2(gabf[6], gabf[7], gab2[3]);

    float vals[NSCAL];
    vals[0] = n; vals[1] = m1; vals[2] = m2; vals[3] = m3; vals[4] = m4;
    #pragma unroll
    for (int f = 0; f < 8; f++) vals[5 + f] = gabf[f];
    #pragma unroll
    for (int k = 0; k < 6; k++) vals[13 + k] = lbp[k];
    #pragma unroll
    for (int a = 0; a < 3; a++) {
        vals[19 + 3 * a] = gs[a];
        vals[20 + 3 * a] = gc[a];
        vals[21 + 3 * a] = gh[a];
    }

    #pragma unroll
    for (int k = 0; k < NSCAL; k++) {
        float v = vals[k];
        #pragma unroll
        for (int o = 16; o > 0; o >>= 1) v += __shfl_down_sync(0xffffffffu, v, o);
        if (lane == 0) red[k][warp] = v;
    }
    __syncthreads();

    if (tid < NSCAL) {
        double acc = 0.0;
        #pragma unroll
        for (int w = 0; w < 8; w++) acc += (double)red[tid][w];
        atomicAdd(&g_acc[b][tid], acc);
    }

    // ---- histogram reduction: warp w handles bins w, w+8, ... ----
    for (int bbin = warp; bbin < 50; bbin += 8) {
        const unsigned* p = (const unsigned*)&h16[bbin * HPITCH];
        unsigned s = 0;
        #pragma unroll
        for (int k = 0; k < 4; k++) {
            unsigned v = p[lane * 4 + k];
            s += (v & 0xffffu) + (v >> 16);
        }
        #pragma unroll
        for (int o = 16; o > 0; o >>= 1) s += __shfl_down_sync(0xffffffffu, s, o);
        if (lane == 0) atomicAdd(&g_acc[b][NSCAL + bbin], (double)s);
    }
}

// ============================================================
// Finalize: one warp per batch (4 blocks x 32 threads).
// ============================================================
__global__ void finalize_kernel(float* __restrict__ out) {
    const int b = blockIdx.x;
    const int lane = threadIdx.x;
    const double* a = g_acc[b];

    double tot = 0.0;
    for (int k = lane; k < 50; k += 32) tot += a[NSCAL + k];
    #pragma unroll
    for (int o = 16; o > 0; o >>= 1) tot += __shfl_down_sync(0xffffffffu, tot, o);
    tot = __shfl_sync(0xffffffffu, tot, 0);
    tot += 1e-8;

    double ent = 0.0;
    for (int k = lane; k < 50; k += 32) {
        double p = a[NSCAL + k] / tot;
        ent -= p * log(p + 1e-8);
    }
    #pragma unroll
    for (int o = 16; o > 0; o >>= 1) ent += __shfl_down_sync(0xffffffffu, ent, o);

    if (lane == 0) {
        double nv = a[0];
        double nn = nv > 1.0 ? nv : 1.0;
        double mu = a[1] / nn;
        double M2 = a[2] - 2.0 * mu * a[1] + mu * mu * nv;
        double nm1 = (nv - 1.0) > 1.0 ? (nv - 1.0) : 1.0;
        double var = M2 / nm1;
        double sigma = sqrt(var) + 1e-8;
        double M3 = a[3] - 3.0 * mu * a[2] + 3.0 * mu * mu * a[1] - mu * mu * mu * nv;
        double M4 = a[4] - 4.0 * mu * a[3] + 6.0 * mu * mu * a[2]
                  - 4.0 * mu * mu * mu * a[1] + mu * mu * mu * mu * nv;
        double sg3 = sigma * sigma * sigma;
        double skew = (M3 / sg3) / nn;
        double kurt = (M4 / (sg3 * sigma)) / nn - 3.0;
        double valid = (nv >= 10.0) ? 1.0 : 0.0;

        float* o = out + b * 25;
        o[0] = (float)(mu * valid);
        o[1] = (float)(sigma * valid);
        o[2] = (float)(skew * valid);
        o[3] = (float)(kurt * valid);
        o[4] = (float)(ent * valid);
        for (int f = 0; f < 8; f++) o[5 + f] = (float)(a[5 + f] / nn);
        for (int k = 0; k < 6; k++) o[13 + k] = (float)(a[13 + k] / nn);
        for (int ax = 0; ax < 3; ax++) {
            double s = a[19 + 3 * ax];
            double ss = s > 1.0 ? s : 1.0;
            double ok = (s >= 4.0) ? 1.0 : 0.0;
            o[19 + 2 * ax]     = (float)((a[20 + 3 * ax] / ss) * ok);
            o[19 + 2 * ax + 1] = (float)((a[21 + 3 * ax] / ss) * ok);
        }
    }
}

extern "C" void kernel_launch(void* const* d_in, const int* in_sizes, int n_in,
                              void* d_out, int out_size) {
    const float* x  = (const float*)d_in[0];
    const float* m  = (const float*)d_in[1];
    const float* gf = (const float*)d_in[2];

    zero_kernel<<<1, 320>>>();

    dim3 grid(WW / TXX, HH / TYV, BB * 4);  // (5, 10, 16) = 800 CTAs
    dim3 blk(TXX, 8);
    fused_kernel<<<grid, blk>>>(x, m, gf);

    finalize_kernel<<<BB, 32>>>((float*)d_out);
}

// round 15
// speedup vs baseline: 1.0637x; 1.0637x over previous
#include <cuda_runtime.h>
#include <math.h>

#define BB 4
#define DD 96
#define HH 160
#define WW 160
#define HW (HH*WW)
#define NSCAL 28
#define NACC  78

// Global accumulators (double); zeroed by zero_kernel each launch.
__device__ double g_acc[BB][80];

typedef unsigned long long u64t;
__device__ __forceinline__ u64t pack2(float lo, float hi) {
    u64t r; asm("mov.b64 %0,{%1,%2};" : "=l"(r) : "f"(lo), "f"(hi)); return r;
}
__device__ __forceinline__ void unpack2(float& lo, float& hi, u64t v) {
    asm("mov.b64 {%0,%1},%2;" : "=f"(lo), "=f"(hi) : "l"(v));
}
__device__ __forceinline__ void fma2(u64t& d, u64t a, u64t b) {
    asm("fma.rn.f32x2 %0,%1,%2,%0;" : "+l"(d) : "l"(a), "l"(b));
}

__global__ void zero_kernel() {
    int i = threadIdx.x;
    if (i < BB * 80) ((double*)g_acc)[i] = 0.0;
}

// ============================================================
// Fused kernel (R13 structure: two barriers per z, proven best).
// Smem shrunk: 3-slot xsh/msk rings (slot q0 never read since
// center-column register rotation) + u8 per-thread histogram
// (max count 48 < 255). 56.3 -> 38.6 KB => L1D 59 -> 112 KB.
// ============================================================
#define TXX 32
#define TYV 16            // voxel rows per tile
#define HR  (TYV + 2)     // 18 halo rows
#define HC  (TXX + 2)     // 34 halo cols
#define ANL (HR * HC)     // 612
#define ZCH 24
#define HPITCH 260        // u8 row pitch (256 threads + 4 pad, /4 aligned)

__global__ __launch_bounds__(256, 3)
void fused_kernel(const float* __restrict__ X, const float* __restrict__ M,
                  const float* __restrict__ GF) {
    __shared__ float xsh[3][HR][HC];
    __shared__ float msk[3][HR][HC];
    __shared__ float2 aux[2][HR][HC];            // (t, s)
    __shared__ unsigned char h8[50 * HPITCH];    // per-thread histogram
    __shared__ float red[NSCAL][8];
    __shared__ float wsm[48];                    // w[8][5] + cf[8]

    const int tx = threadIdx.x, ty = threadIdx.y;     // ty in 0..7
    const int tid = ty * TXX + tx;
    const int warp = tid >> 5, lane = tid & 31;
    const int x0 = blockIdx.x * TXX, y0 = blockIdx.y * TYV;
    const int b = blockIdx.z >> 2;
    const int zs = (blockIdx.z & 3) * ZCH;   // multiple of 24 -> %3==0, even
    const float* Xb = X + (size_t)b * DD * HW;
    const float* Mb = M + (size_t)b * DD * HW;
    const float A = 0.13533528323661270f;  // exp(-2)

    // zero per-thread histogram (u32 strided)
    {
        unsigned* h32 = (unsigned*)h8;
        #pragma unroll
        for (int i = tid; i < 50 * HPITCH / 4; i += 256) h32[i] = 0u;
    }

    // derive weights (threads 0..7, one filter each):
    // F[dz][j] = gz[dz]*u[j] - c, gz=[a,1,a] => u[j]=(F1-F0)/(1-a)
    // conv = sum_sym ubar_k * tsym_k - cf*box ; u symmetric (u[j]==u[8-j])
    if (tid < 8) {
        float u[9], cacc = 0.0f;
        #pragma unroll
        for (int j = 0; j < 9; j++) {
            float F1 = GF[tid * 27 + 9 + j];
            float F0 = GF[tid * 27 + j];
            u[j] = (F1 - F0) * (1.0f / (1.0f - A));
            cacc += (u[j] - F1);
        }
        wsm[40 + tid] = cacc * (1.0f / 9.0f);
        wsm[tid * 5 + 0] = (u[0] + u[8]) * 0.5f;
        wsm[tid * 5 + 1] = (u[1] + u[7]) * 0.5f;
        wsm[tid * 5 + 2] = (u[2] + u[6]) * 0.5f;
        wsm[tid * 5 + 3] = (u[3] + u[5]) * 0.5f;
        wsm[tid * 5 + 4] = u[4];
    }

    // halo-load slots (3 segments, z-invariant)
    int loff[3]; bool lval[3];
    #pragma unroll
    for (int s = 0; s < 3; s++) {
        int i = tid + s * 256;
        bool ok = (i < ANL);
        int ry = ok ? i / HC : 0, rx = ok ? i % HC : 0;
        int gy = y0 + ry - 1, gx = x0 + rx - 1;
        lval[s] = ok && gy >= 0 && gy < HH && gx >= 0 && gx < WW;
        loff[s] = gy * WW + gx;
    }

    float xmR[3], xcR[3];

    // preload: x(zs-1)->xsh[2] (mask(zs-1) never read, not stored),
    // plane zs -> slot 0, zs+1 -> slot 1; aux(zs) -> slot 0.
    #pragma unroll
    for (int s = 0; s < 3; s++) {
        int i = tid + s * 256;
        if (i < ANL) {
            float xv_m = 0, xv_0 = 0, mv_0 = 0, xv_p = 0, mv_p = 0;
            if (lval[s]) {
                if (zs > 0) xv_m = __ldg(Xb + (size_t)(zs - 1) * HW + loff[s]);
                xv_0 = __ldg(Xb + (size_t)zs * HW + loff[s]);
                mv_0 = __ldg(Mb + (size_t)zs * HW + loff[s]);
                xv_p = __ldg(Xb + (size_t)(zs + 1) * HW + loff[s]);
                mv_p = __ldg(Mb + (size_t)(zs + 1) * HW + loff[s]);
            }
            (&xsh[2][0][0])[i] = xv_m;
            (&xsh[0][0][0])[i] = xv_0;  (&msk[0][0][0])[i] = mv_0;
            (&xsh[1][0][0])[i] = xv_p;  (&msk[1][0][0])[i] = mv_p;
            float mp2 = xv_m + xv_p;
            (&aux[0][0][0])[i] = make_float2(fmaf(A, mp2, xv_0), mp2 + xv_0);
            xmR[s] = xv_0;
            xcR[s] = xv_p;
        }
    }

    const u64t ABSM = 0x7FFFFFFF7FFFFFFFull;
    u64t gab2[4] = {0ull, 0ull, 0ull, 0ull};
    float n = 0, m1 = 0, m2 = 0, m3 = 0, m4 = 0;
    float lbp[6] = {0, 0, 0, 0, 0, 0};
    float gs[3] = {0, 0, 0}, gc[3] = {0, 0, 0}, gh[3] = {0, 0, 0};

    const int vy0 = 2 * ty + 1, vy1 = 2 * ty + 2, txc = tx + 1;

    __syncthreads();   // hist zero + weights + preload visible

    // packed weights: pair filters (2p, 2p+1)
    u64t w2[20], cf2[4];
    #pragma unroll
    for (int p = 0; p < 4; p++) {
        #pragma unroll
        for (int k = 0; k < 5; k++)
            w2[p * 5 + k] = pack2(wsm[(2 * p) * 5 + k], wsm[(2 * p + 1) * 5 + k]);
        cf2[p] = pack2(-wsm[40 + 2 * p], -wsm[40 + 2 * p + 1]);
    }

    // center-column register rotation state (c, xdn, mc per voxel)
    float cc0 = xsh[0][vy0][txc], cc1 = xsh[0][vy1][txc];
    float cd0 = xsh[2][vy0][txc], cd1 = xsh[2][vy1][txc];
    float cm0 = msk[0][vy0][txc], cm1 = msk[0][vy1][txc];

    // 3-slot ring indices: read q1,q2; write sw. zs%3==0.
    int q1 = 0, q2 = 1, sw = 2;
    int az = 0;

    for (int z = zs; z < zs + ZCH; z++) {
        // issue LDGs for plane z+2 early
        float xn[3] = {0, 0, 0}, mn[3] = {0, 0, 0};
        {
            int zq = z + 2;
            if (zq < DD) {
                const float* Px = Xb + (size_t)zq * HW;
                const float* Pm = Mb + (size_t)zq * HW;
                #pragma unroll
                for (int s = 0; s < 3; s++)
                    if (lval[s]) { xn[s] = __ldg(Px + loff[s]); mn[s] = __ldg(Pm + loff[s]); }
            }
        }

        // ---- aux window: 4 rows x 3 cols (12 LDS.64) covers both voxels ----
        float t[4][3], rowS[4];
        #pragma unroll
        for (int r = 0; r < 4; r++) {
            float2 a0 = aux[az][2 * ty + r][tx    ];
            float2 a1 = aux[az][2 * ty + r][tx + 1];
            float2 a2 = aux[az][2 * ty + r][tx + 2];
            t[r][0] = a0.x; t[r][1] = a1.x; t[r][2] = a2.x;
            rowS[r] = a0.y + a1.y + a2.y;
        }

        // ---- raw reads (split x / m); center column from registers ----
        float xv0 = xsh[q1][vy0 - 1][txc];
        float xv1 = cc0;
        float xv2 = cc1;
        float xv3 = xsh[q1][vy1 + 1][txc];
        float xxm0 = xsh[q1][vy0][tx], xxp0 = xsh[q1][vy0][tx + 2];
        float xxm1 = xsh[q1][vy1][tx], xxp1 = xsh[q1][vy1][tx + 2];
        float xup0 = xsh[q2][vy0][txc], xup1 = xsh[q2][vy1][txc];
        float xdn0 = cd0, xdn1 = cd1;
        float mc0 = cm0, mc1 = cm1;
        float myp1 = msk[q1][vy1 + 1][txc];
        float mxp0 = msk[q1][vy0][tx + 2], mxp1 = msk[q1][vy1][tx + 2];
        float mzp0 = msk[q2][vy0][txc], mzp1 = msk[q2][vy1][txc];

        #define DO_VOXEL(R, CC, MC, XUP, XDN, XYP, XYM, XXP, XXM, MZP, MYP, MXP)          \
        {                                                                                  \
            float C  = t[R][0] + t[R + 2][2];                                              \
            float CA = t[R][2] + t[R + 2][0];                                              \
            float Ey = t[R][1] + t[R + 2][1];                                              \
            float Ex = t[R + 1][0] + t[R + 1][2];                                          \
            float ct = t[R + 1][1];                                                        \
            float box = rowS[R] + rowS[R + 1] + rowS[R + 2];                               \
            u64t T0 = pack2(C, C),  T1 = pack2(Ey, Ey), T2 = pack2(CA, CA);                \
            u64t T3 = pack2(Ex, Ex), T4 = pack2(ct, ct), BX = pack2(box, box);             \
            u64t mcp = pack2(MC, MC);                                                      \
            _Pragma("unroll")                                                              \
            for (int p = 0; p < 4; p++) {                                                  \
                u64t acc = 0ull;                                                           \
                fma2(acc, w2[p * 5 + 0], T0);                                              \
                fma2(acc, w2[p * 5 + 1], T1);                                              \
                fma2(acc, w2[p * 5 + 2], T2);                                              \
                fma2(acc, w2[p * 5 + 3], T3);                                              \
                fma2(acc, w2[p * 5 + 4], T4);                                              \
                fma2(acc, cf2[p], BX);                                                     \
                acc &= ABSM;                                                               \
                fma2(gab2[p], acc, mcp);                                                   \
            }                                                                              \
            float c2 = CC * CC;                                                            \
            n += MC;                                                                       \
            m1 = fmaf(MC, CC, m1);                                                         \
            m2 = fmaf(MC, c2, m2);                                                         \
            float mcc = MC * CC;                                                           \
            m3 = fmaf(mcc, c2, m3);                                                        \
            m4 = fmaf(MC * c2, c2, m4);                                                    \
            if (MC > 0.5f && CC >= -1.0f && CC <= 1.0f) {                                  \
                int bi = (int)floorf(__fmul_rn(__fadd_rn(CC, 1.0f), 25.0f));               \
                bi = min(max(bi, 0), 49);                                                  \
                h8[bi * HPITCH + tid] += 1;                                                \
            }                                                                              \
            bool mb = MC > 0.5f;                                                           \
            if (mb) {                                                                      \
                lbp[0] += (CC - XUP > 0.0f) ? 1.0f : 0.0f;                                 \
                lbp[1] += (CC - XDN > 0.0f) ? 1.0f : 0.0f;                                 \
                lbp[2] += (CC - XYP > 0.0f) ? 1.0f : 0.0f;                                 \
                lbp[3] += (CC - XYM > 0.0f) ? 1.0f : 0.0f;                                 \
                lbp[4] += (CC - XXP > 0.0f) ? 1.0f : 0.0f;                                 \
                lbp[5] += (CC - XXM > 0.0f) ? 1.0f : 0.0f;                                 \
            }                                                                              \
            {                                                                              \
                float mp = (mb && MZP > 0.5f) ? 1.0f : 0.0f;                               \
                float d = CC - XUP, dd = d * d;                                            \
                gs[0] += mp;                                                               \
                gc[0] = fmaf(mp, dd, gc[0]);                                               \
                gh[0] = fmaf(mp, __fdividef(1.0f, 1.0f + dd), gh[0]);                      \
            }                                                                              \
            {                                                                              \
                float mp = (mb && MYP > 0.5f) ? 1.0f : 0.0f;                               \
                float d = CC - XYP, dd = d * d;                                            \
                gs[1] += mp;                                                               \
                gc[1] = fmaf(mp, dd, gc[1]);                                               \
                gh[1] = fmaf(mp, __fdividef(1.0f, 1.0f + dd), gh[1]);                      \
            }                                                                              \
            {                                                                              \
                float mp = (mb && MXP > 0.5f) ? 1.0f : 0.0f;                               \
                float d = CC - XXP, dd = d * d;                                            \
                gs[2] += mp;                                                               \
                gc[2] = fmaf(mp, dd, gc[2]);                                               \
                gh[2] = fmaf(mp, __fdividef(1.0f, 1.0f + dd), gh[2]);                      \
            }                                                                              \
        }

        DO_VOXEL(0, xv1, mc0, xup0, xdn0, xv2, xv0, xxp0, xxm0, mzp0, mc1,  mxp0)
        DO_VOXEL(1, xv2, mc1, xup1, xdn1, xv3, xv1, xxp1, xxm1, mzp1, myp1, mxp1)
        #undef DO_VOXEL

        // rotate center-column registers
        cd0 = cc0; cd1 = cc1;
        cc0 = xup0; cc1 = xup1;
        cm0 = mzp0; cm1 = mzp1;

        __syncthreads();   // all reads of current plane done before staging

        // ---- stage: aux(z+1) from register history; raw(z+2) -> slot sw ----
        {
            float* bx = &xsh[sw][0][0];
            float* bm = &msk[sw][0][0];
            float2* ba = &aux[az ^ 1][0][0];
            #pragma unroll
            for (int s = 0; s < 3; s++) {
                int i = tid + s * 256;
                if (s < 2 || i < ANL) {
                    float mp2 = xmR[s] + xn[s];
                    ba[i] = make_float2(fmaf(A, mp2, xcR[s]), mp2 + xcR[s]);
                    bx[i] = xn[s];
                    bm[i] = mn[s];
                    xmR[s] = xcR[s]; xcR[s] = xn[s];
                }
            }
        }
        __syncthreads();   // staging visible before next-plane reads

        // rotate ring indices
        int tq = q1; q1 = q2; q2 = sw; sw = tq;
        az ^= 1;
    }

    // ---- block reduction of 28 scalars ----
    float gabf[8];
    unpack2(gabf[0], gabf[1], gab2[0]);
    unpack2(gabf[2], gabf[3], gab2[1]);
    unpack2(gabf[4], gabf[5], gab2[2]);
    unpack2(gabf[6], gabf[7], gab2[3]);

    float vals[NSCAL];
    vals[0] = n; vals[1] = m1; vals[2] = m2; vals[3] = m3; vals[4] = m4;
    #pragma unroll
    for (int f = 0; f < 8; f++) vals[5 + f] = gabf[f];
    #pragma unroll
    for (int k = 0; k < 6; k++) vals[13 + k] = lbp[k];
    #pragma unroll
    for (int a = 0; a < 3; a++) {
        vals[19 + 3 * a] = gs[a];
        vals[20 + 3 * a] = gc[a];
        vals[21 + 3 * a] = gh[a];
    }

    #pragma unroll
    for (int k = 0; k < NSCAL; k++) {
        float v = vals[k];
        #pragma unroll
        for (int o = 16; o > 0; o >>= 1) v += __shfl_down_sync(0xffffffffu, v, o);
        if (lane == 0) red[k][warp] = v;
    }
    __syncthreads();

    if (tid < NSCAL) {
        double acc = 0.0;
        #pragma unroll
        for (int w = 0; w < 8; w++) acc += (double)red[tid][w];
        atomicAdd(&g_acc[b][tid], acc);
    }

    // ---- histogram reduction: warp w handles bins w, w+8, ...
    // 256 u8 counters per bin = 64 u32; lane sums 2 u32 via dp4a. ----
    for (int bbin = warp; bbin < 50; bbin += 8) {
        const unsigned* p = (const unsigned*)(h8 + bbin * HPITCH);
        unsigned s = 0;
        s = __dp4a(p[lane * 2 + 0], 0x01010101u, s);
        s = __dp4a(p[lane * 2 + 1], 0x01010101u, s);
        #pragma unroll
        for (int o = 16; o > 0; o >>= 1) s += __shfl_down_sync(0xffffffffu, s, o);
        if (lane == 0) atomicAdd(&g_acc[b][NSCAL + bbin], (double)s);
    }
}

// ============================================================
// Finalize: one warp per batch (4 blocks x 32 threads).
// ============================================================
__global__ void finalize_kernel(float* __restrict__ out) {
    const int b = blockIdx.x;
    const int lane = threadIdx.x;
    const double* a = g_acc[b];

    double tot = 0.0;
    for (int k = lane; k < 50; k += 32) tot += a[NSCAL + k];
    #pragma unroll
    for (int o = 16; o > 0; o >>= 1) tot += __shfl_down_sync(0xffffffffu, tot, o);
    tot = __shfl_sync(0xffffffffu, tot, 0);
    tot += 1e-8;

    double ent = 0.0;
    for (int k = lane; k < 50; k += 32) {
        double p = a[NSCAL + k] / tot;
        ent -= p * log(p + 1e-8);
    }
    #pragma unroll
    for (int o = 16; o > 0; o >>= 1) ent += __shfl_down_sync(0xffffffffu, ent, o);

    if (lane == 0) {
        double nv = a[0];
        double nn = nv > 1.0 ? nv : 1.0;
        double mu = a[1] / nn;
        double M2 = a[2] - 2.0 * mu * a[1] + mu * mu * nv;
        double nm1 = (nv - 1.0) > 1.0 ? (nv - 1.0) : 1.0;
        double var = M2 / nm1;
        double sigma = sqrt(var) + 1e-8;
        double M3 = a[3] - 3.0 * mu * a[2] + 3.0 * mu * mu * a[1] - mu * mu * mu * nv;
        double M4 = a[4] - 4.0 * mu * a[3] + 6.0 * mu * mu * a[2]
                  - 4.0 * mu * mu * mu * a[1] + mu * mu * mu * mu * nv;
        double sg3 = sigma * sigma * sigma;
        double skew = (M3 / sg3) / nn;
        double kurt = (M4 / (sg3 * sigma)) / nn - 3.0;
        double valid = (nv >= 10.0) ? 1.0 : 0.0;

        float* o = out + b * 25;
        o[0] = (float)(mu * valid);
        o[1] = (float)(sigma * valid);
        o[2] = (float)(skew * valid);
        o[3] = (float)(kurt * valid);
        o[4] = (float)(ent * valid);
        for (int f = 0; f < 8; f++) o[5 + f] = (float)(a[5 + f] / nn);
        for (int k = 0; k < 6; k++) o[13 + k] = (float)(a[13 + k] / nn);
        for (int ax = 0; ax < 3; ax++) {
            double s = a[19 + 3 * ax];
            double ss = s > 1.0 ? s : 1.0;
            double ok = (s >= 4.0) ? 1.0 : 0.0;
            o[19 + 2 * ax]     = (float)((a[20 + 3 * ax] / ss) * ok);
            o[19 + 2 * ax + 1] = (float)((a[21 + 3 * ax] / ss) * ok);
        }
    }
}

extern "C" void kernel_launch(void* const* d_in, const int* in_sizes, int n_in,
                              void* d_out, int out_size) {
    const float* x  = (const float*)d_in[0];
    const float* m  = (const float*)d_in[1];
    const float* gf = (const float*)d_in[2];

    zero_kernel<<<1, 320>>>();

    dim3 grid(WW / TXX, HH / TYV, BB * 4);  // (5, 10, 16) = 800 CTAs
    dim3 blk(TXX, 8);
    fused_kernel<<<grid, blk>>>(x, m, gf);

    finalize_kernel<<<BB, 32>>>((float*)d_out);
}

// round 16
// speedup vs baseline: 1.0734x; 1.0092x over previous
#include <cuda_runtime.h>
#include <math.h>

#define BB 4
#define DD 96
#define HH 160
#define WW 160
#define HW (HH*WW)
#define NSCAL 28
#define NACC  78

// Global accumulators (double). Zero-initialized at module load;
// finalize_kernel re-zeroes after reading, so every subsequent
// launch/replay starts from zero. No zero_kernel needed.
__device__ double g_acc[BB][80];

typedef unsigned long long u64t;
__device__ __forceinline__ u64t pack2(float lo, float hi) {
    u64t r; asm("mov.b64 %0,{%1,%2};" : "=l"(r) : "f"(lo), "f"(hi)); return r;
}
__device__ __forceinline__ void unpack2(float& lo, float& hi, u64t v) {
    asm("mov.b64 {%0,%1},%2;" : "=f"(lo), "=f"(hi) : "l"(v));
}
__device__ __forceinline__ void fma2(u64t& d, u64t a, u64t b) {
    asm("fma.rn.f32x2 %0,%1,%2,%0;" : "+l"(d) : "l"(a), "l"(b));
}

// ============================================================
// Fused kernel (R15 structure, byte-identical loop).
// ============================================================
#define TXX 32
#define TYV 16            // voxel rows per tile
#define HR  (TYV + 2)     // 18 halo rows
#define HC  (TXX + 2)     // 34 halo cols
#define ANL (HR * HC)     // 612
#define ZCH 24
#define HPITCH 260        // u8 row pitch (256 threads + 4 pad, /4 aligned)

__global__ __launch_bounds__(256, 3)
void fused_kernel(const float* __restrict__ X, const float* __restrict__ M,
                  const float* __restrict__ GF) {
    __shared__ float xsh[3][HR][HC];
    __shared__ float msk[3][HR][HC];
    __shared__ float2 aux[2][HR][HC];            // (t, s)
    __shared__ unsigned char h8[50 * HPITCH];    // per-thread histogram
    __shared__ float red[NSCAL][8];
    __shared__ float wsm[48];                    // w[8][5] + cf[8]

    const int tx = threadIdx.x, ty = threadIdx.y;     // ty in 0..7
    const int tid = ty * TXX + tx;
    const int warp = tid >> 5, lane = tid & 31;
    const int x0 = blockIdx.x * TXX, y0 = blockIdx.y * TYV;
    const int b = blockIdx.z >> 2;
    const int zs = (blockIdx.z & 3) * ZCH;   // multiple of 24 -> %3==0, even
    const float* Xb = X + (size_t)b * DD * HW;
    const float* Mb = M + (size_t)b * DD * HW;
    const float A = 0.13533528323661270f;  // exp(-2)

    // zero per-thread histogram (u32 strided)
    {
        unsigned* h32 = (unsigned*)h8;
        #pragma unroll
        for (int i = tid; i < 50 * HPITCH / 4; i += 256) h32[i] = 0u;
    }

    // derive weights (threads 0..7, one filter each):
    // F[dz][j] = gz[dz]*u[j] - c, gz=[a,1,a] => u[j]=(F1-F0)/(1-a)
    // conv = sum_sym ubar_k * tsym_k - cf*box ; u symmetric (u[j]==u[8-j])
    if (tid < 8) {
        float u[9], cacc = 0.0f;
        #pragma unroll
        for (int j = 0; j < 9; j++) {
            float F1 = GF[tid * 27 + 9 + j];
            float F0 = GF[tid * 27 + j];
            u[j] = (F1 - F0) * (1.0f / (1.0f - A));
            cacc += (u[j] - F1);
        }
        wsm[40 + tid] = cacc * (1.0f / 9.0f);
        wsm[tid * 5 + 0] = (u[0] + u[8]) * 0.5f;
        wsm[tid * 5 + 1] = (u[1] + u[7]) * 0.5f;
        wsm[tid * 5 + 2] = (u[2] + u[6]) * 0.5f;
        wsm[tid * 5 + 3] = (u[3] + u[5]) * 0.5f;
        wsm[tid * 5 + 4] = u[4];
    }

    // halo-load slots (3 segments, z-invariant)
    int loff[3]; bool lval[3];
    #pragma unroll
    for (int s = 0; s < 3; s++) {
        int i = tid + s * 256;
        bool ok = (i < ANL);
        int ry = ok ? i / HC : 0, rx = ok ? i % HC : 0;
        int gy = y0 + ry - 1, gx = x0 + rx - 1;
        lval[s] = ok && gy >= 0 && gy < HH && gx >= 0 && gx < WW;
        loff[s] = gy * WW + gx;
    }

    float xmR[3], xcR[3];

    // preload: x(zs-1)->xsh[2] (mask(zs-1) never read, not stored),
    // plane zs -> slot 0, zs+1 -> slot 1; aux(zs) -> slot 0.
    #pragma unroll
    for (int s = 0; s < 3; s++) {
        int i = tid + s * 256;
        if (i < ANL) {
            float xv_m = 0, xv_0 = 0, mv_0 = 0, xv_p = 0, mv_p = 0;
            if (lval[s]) {
                if (zs > 0) xv_m = __ldg(Xb + (size_t)(zs - 1) * HW + loff[s]);
                xv_0 = __ldg(Xb + (size_t)zs * HW + loff[s]);
                mv_0 = __ldg(Mb + (size_t)zs * HW + loff[s]);
                xv_p = __ldg(Xb + (size_t)(zs + 1) * HW + loff[s]);
                mv_p = __ldg(Mb + (size_t)(zs + 1) * HW + loff[s]);
            }
            (&xsh[2][0][0])[i] = xv_m;
            (&xsh[0][0][0])[i] = xv_0;  (&msk[0][0][0])[i] = mv_0;
            (&xsh[1][0][0])[i] = xv_p;  (&msk[1][0][0])[i] = mv_p;
            float mp2 = xv_m + xv_p;
            (&aux[0][0][0])[i] = make_float2(fmaf(A, mp2, xv_0), mp2 + xv_0);
            xmR[s] = xv_0;
            xcR[s] = xv_p;
        }
    }

    const u64t ABSM = 0x7FFFFFFF7FFFFFFFull;
    u64t gab2[4] = {0ull, 0ull, 0ull, 0ull};
    float n = 0, m1 = 0, m2 = 0, m3 = 0, m4 = 0;
    float lbp[6] = {0, 0, 0, 0, 0, 0};
    float gs[3] = {0, 0, 0}, gc[3] = {0, 0, 0}, gh[3] = {0, 0, 0};

    const int vy0 = 2 * ty + 1, vy1 = 2 * ty + 2, txc = tx + 1;

    __syncthreads();   // hist zero + weights + preload visible

    // packed weights: pair filters (2p, 2p+1)
    u64t w2[20], cf2[4];
    #pragma unroll
    for (int p = 0; p < 4; p++) {
        #pragma unroll
        for (int k = 0; k < 5; k++)
            w2[p * 5 + k] = pack2(wsm[(2 * p) * 5 + k], wsm[(2 * p + 1) * 5 + k]);
        cf2[p] = pack2(-wsm[40 + 2 * p], -wsm[40 + 2 * p + 1]);
    }

    // center-column register rotation state (c, xdn, mc per voxel)
    float cc0 = xsh[0][vy0][txc], cc1 = xsh[0][vy1][txc];
    float cd0 = xsh[2][vy0][txc], cd1 = xsh[2][vy1][txc];
    float cm0 = msk[0][vy0][txc], cm1 = msk[0][vy1][txc];

    // 3-slot ring indices: read q1,q2; write sw. zs%3==0.
    int q1 = 0, q2 = 1, sw = 2;
    int az = 0;

    for (int z = zs; z < zs + ZCH; z++) {
        // issue LDGs for plane z+2 early
        float xn[3] = {0, 0, 0}, mn[3] = {0, 0, 0};
        {
            int zq = z + 2;
            if (zq < DD) {
                const float* Px = Xb + (size_t)zq * HW;
                const float* Pm = Mb + (size_t)zq * HW;
                #pragma unroll
                for (int s = 0; s < 3; s++)
                    if (lval[s]) { xn[s] = __ldg(Px + loff[s]); mn[s] = __ldg(Pm + loff[s]); }
            }
        }

        // ---- aux window: 4 rows x 3 cols (12 LDS.64) covers both voxels ----
        float t[4][3], rowS[4];
        #pragma unroll
        for (int r = 0; r < 4; r++) {
            float2 a0 = aux[az][2 * ty + r][tx    ];
            float2 a1 = aux[az][2 * ty + r][tx + 1];
            float2 a2 = aux[az][2 * ty + r][tx + 2];
            t[r][0] = a0.x; t[r][1] = a1.x; t[r][2] = a2.x;
            rowS[r] = a0.y + a1.y + a2.y;
        }

        // ---- raw reads (split x / m); center column from registers ----
        float xv0 = xsh[q1][vy0 - 1][txc];
        float xv1 = cc0;
        float xv2 = cc1;
        float xv3 = xsh[q1][vy1 + 1][txc];
        float xxm0 = xsh[q1][vy0][tx], xxp0 = xsh[q1][vy0][tx + 2];
        float xxm1 = xsh[q1][vy1][tx], xxp1 = xsh[q1][vy1][tx + 2];
        float xup0 = xsh[q2][vy0][txc], xup1 = xsh[q2][vy1][txc];
        float xdn0 = cd0, xdn1 = cd1;
        float mc0 = cm0, mc1 = cm1;
        float myp1 = msk[q1][vy1 + 1][txc];
        float mxp0 = msk[q1][vy0][tx + 2], mxp1 = msk[q1][vy1][tx + 2];
        float mzp0 = msk[q2][vy0][txc], mzp1 = msk[q2][vy1][txc];

        #define DO_VOXEL(R, CC, MC, XUP, XDN, XYP, XYM, XXP, XXM, MZP, MYP, MXP)          \
        {                                                                                  \
            float C  = t[R][0] + t[R + 2][2];                                              \
            float CA = t[R][2] + t[R + 2][0];                                              \
            float Ey = t[R][1] + t[R + 2][1];                                              \
            float Ex = t[R + 1][0] + t[R + 1][2];                                          \
            float ct = t[R + 1][1];                                                        \
            float box = rowS[R] + rowS[R + 1] + rowS[R + 2];                               \
            u64t T0 = pack2(C, C),  T1 = pack2(Ey, Ey), T2 = pack2(CA, CA);                \
            u64t T3 = pack2(Ex, Ex), T4 = pack2(ct, ct), BX = pack2(box, box);             \
            u64t mcp = pack2(MC, MC);                                                      \
            _Pragma("unroll")                                                              \
            for (int p = 0; p < 4; p++) {                                                  \
                u64t acc = 0ull;                                                           \
                fma2(acc, w2[p * 5 + 0], T0);                                              \
                fma2(acc, w2[p * 5 + 1], T1);                                              \
                fma2(acc, w2[p * 5 + 2], T2);                                              \
                fma2(acc, w2[p * 5 + 3], T3);                                              \
                fma2(acc, w2[p * 5 + 4], T4);                                              \
                fma2(acc, cf2[p], BX);                                                     \
                acc &= ABSM;                                                               \
                fma2(gab2[p], acc, mcp);                                                   \
            }                                                                              \
            float c2 = CC * CC;                                                            \
            n += MC;                                                                       \
            m1 = fmaf(MC, CC, m1);                                                         \
            m2 = fmaf(MC, c2, m2);                                                         \
            float mcc = MC * CC;                                                           \
            m3 = fmaf(mcc, c2, m3);                                                        \
            m4 = fmaf(MC * c2, c2, m4);                                                    \
            if (MC > 0.5f && CC >= -1.0f && CC <= 1.0f) {                                  \
                int bi = (int)floorf(__fmul_rn(__fadd_rn(CC, 1.0f), 25.0f));               \
                bi = min(max(bi, 0), 49);                                                  \
                h8[bi * HPITCH + tid] += 1;                                                \
            }                                                                              \
            bool mb = MC > 0.5f;                                                           \
            if (mb) {                                                                      \
                lbp[0] += (CC - XUP > 0.0f) ? 1.0f : 0.0f;                                 \
                lbp[1] += (CC - XDN > 0.0f) ? 1.0f : 0.0f;                                 \
                lbp[2] += (CC - XYP > 0.0f) ? 1.0f : 0.0f;                                 \
                lbp[3] += (CC - XYM > 0.0f) ? 1.0f : 0.0f;                                 \
                lbp[4] += (CC - XXP > 0.0f) ? 1.0f : 0.0f;                                 \
                lbp[5] += (CC - XXM > 0.0f) ? 1.0f : 0.0f;                                 \
            }                                                                              \
            {                                                                              \
                float mp = (mb && MZP > 0.5f) ? 1.0f : 0.0f;                               \
                float d = CC - XUP, dd = d * d;                                            \
                gs[0] += mp;                                                               \
                gc[0] = fmaf(mp, dd, gc[0]);                                               \
                gh[0] = fmaf(mp, __fdividef(1.0f, 1.0f + dd), gh[0]);                      \
            }                                                                              \
            {                                                                              \
                float mp = (mb && MYP > 0.5f) ? 1.0f : 0.0f;                               \
                float d = CC - XYP, dd = d * d;                                            \
                gs[1] += mp;                                                               \
                gc[1] = fmaf(mp, dd, gc[1]);                                               \
                gh[1] = fmaf(mp, __fdividef(1.0f, 1.0f + dd), gh[1]);                      \
            }                                                                              \
            {                                                                              \
                float mp = (mb && MXP > 0.5f) ? 1.0f : 0.0f;                               \
                float d = CC - XXP, dd = d * d;                                            \
                gs[2] += mp;                                                               \
                gc[2] = fmaf(mp, dd, gc[2]);                                               \
                gh[2] = fmaf(mp, __fdividef(1.0f, 1.0f + dd), gh[2]);                      \
            }                                                                              \
        }

        DO_VOXEL(0, xv1, mc0, xup0, xdn0, xv2, xv0, xxp0, xxm0, mzp0, mc1,  mxp0)
        DO_VOXEL(1, xv2, mc1, xup1, xdn1, xv3, xv1, xxp1, xxm1, mzp1, myp1, mxp1)
        #undef DO_VOXEL

        // rotate center-column registers
        cd0 = cc0; cd1 = cc1;
        cc0 = xup0; cc1 = xup1;
        cm0 = mzp0; cm1 = mzp1;

        __syncthreads();   // all reads of current plane done before staging

        // ---- stage: aux(z+1) from register history; raw(z+2) -> slot sw ----
        {
            float* bx = &xsh[sw][0][0];
            float* bm = &msk[sw][0][0];
            float2* ba = &aux[az ^ 1][0][0];
            #pragma unroll
            for (int s = 0; s < 3; s++) {
                int i = tid + s * 256;
                if (s < 2 || i < ANL) {
                    float mp2 = xmR[s] + xn[s];
                    ba[i] = make_float2(fmaf(A, mp2, xcR[s]), mp2 + xcR[s]);
                    bx[i] = xn[s];
                    bm[i] = mn[s];
                    xmR[s] = xcR[s]; xcR[s] = xn[s];
                }
            }
        }
        __syncthreads();   // staging visible before next-plane reads

        // rotate ring indices
        int tq = q1; q1 = q2; q2 = sw; sw = tq;
        az ^= 1;
    }

    // ---- block reduction of 28 scalars ----
    float gabf[8];
    unpack2(gabf[0], gabf[1], gab2[0]);
    unpack2(gabf[2], gabf[3], gab2[1]);
    unpack2(gabf[4], gabf[5], gab2[2]);
    unpack2(gabf[6], gabf[7], gab2[3]);

    float vals[NSCAL];
    vals[0] = n; vals[1] = m1; vals[2] = m2; vals[3] = m3; vals[4] = m4;
    #pragma unroll
    for (int f = 0; f < 8; f++) vals[5 + f] = gabf[f];
    #pragma unroll
    for (int k = 0; k < 6; k++) vals[13 + k] = lbp[k];
    #pragma unroll
    for (int a = 0; a < 3; a++) {
        vals[19 + 3 * a] = gs[a];
        vals[20 + 3 * a] = gc[a];
        vals[21 + 3 * a] = gh[a];
    }

    #pragma unroll
    for (int k = 0; k < NSCAL; k++) {
        float v = vals[k];
        #pragma unroll
        for (int o = 16; o > 0; o >>= 1) v += __shfl_down_sync(0xffffffffu, v, o);
        if (lane == 0) red[k][warp] = v;
    }
    __syncthreads();

    if (tid < NSCAL) {
        double acc = 0.0;
        #pragma unroll
        for (int w = 0; w < 8; w++) acc += (double)red[tid][w];
        atomicAdd(&g_acc[b][tid], acc);
    }

    // ---- histogram reduction: warp w handles bins w, w+8, ...
    // 256 u8 counters per bin = 64 u32; lane sums 2 u32 via dp4a. ----
    for (int bbin = warp; bbin < 50; bbin += 8) {
        const unsigned* p = (const unsigned*)(h8 + bbin * HPITCH);
        unsigned s = 0;
        s = __dp4a(p[lane * 2 + 0], 0x01010101u, s);
        s = __dp4a(p[lane * 2 + 1], 0x01010101u, s);
        #pragma unroll
        for (int o = 16; o > 0; o >>= 1) s += __shfl_down_sync(0xffffffffu, s, o);
        if (lane == 0) atomicAdd(&g_acc[b][NSCAL + bbin], (double)s);
    }
}

// ============================================================
// Finalize: one warp per batch (4 blocks x 32 threads).
// Reads g_acc into registers, then RE-ZEROES it so the next
// launch/replay starts clean (first run relies on static
// zero-init of device globals).
// ============================================================
__global__ void finalize_kernel(float* __restrict__ out) {
    const int b = blockIdx.x;
    const int lane = threadIdx.x;
    double* a = g_acc[b];

    // load all 80 slots into lane-local registers (<=3 each)
    double v0 = a[lane];
    double v1 = (lane + 32 < 80) ? a[lane + 32] : 0.0;
    double v2 = (lane + 64 < 80) ? a[lane + 64] : 0.0;
    __syncwarp();

    // re-zero for the next launch (all reads above are complete)
    a[lane] = 0.0;
    if (lane + 32 < 80) a[lane + 32] = 0.0;
    if (lane + 64 < 80) a[lane + 64] = 0.0;

    // reconstruct a[] access via shuffles: helper lambda-free approach —
    // gather the 78 values into shared memory of the block instead.
    __shared__ double sa[80];
    sa[lane] = v0;
    if (lane + 32 < 80) sa[lane + 32] = v1;
    if (lane + 64 < 80) sa[lane + 64] = v2;
    __syncwarp();

    double tot = 0.0;
    for (int k = lane; k < 50; k += 32) tot += sa[NSCAL + k];
    #pragma unroll
    for (int o = 16; o > 0; o >>= 1) tot += __shfl_down_sync(0xffffffffu, tot, o);
    tot = __shfl_sync(0xffffffffu, tot, 0);
    tot += 1e-8;

    double ent = 0.0;
    for (int k = lane; k < 50; k += 32) {
        double p = sa[NSCAL + k] / tot;
        ent -= p * log(p + 1e-8);
    }
    #pragma unroll
    for (int o = 16; o > 0; o >>= 1) ent += __shfl_down_sync(0xffffffffu, ent, o);

    if (lane == 0) {
        double nv = sa[0];
        double nn = nv > 1.0 ? nv : 1.0;
        double mu = sa[1] / nn;
        double M2 = sa[2] - 2.0 * mu * sa[1] + mu * mu * nv;
        double nm1 = (nv - 1.0) > 1.0 ? (nv - 1.0) : 1.0;
        double var = M2 / nm1;
        double sigma = sqrt(var) + 1e-8;
        double M3 = sa[3] - 3.0 * mu * sa[2] + 3.0 * mu * mu * sa[1] - mu * mu * mu * nv;
        double M4 = sa[4] - 4.0 * mu * sa[3] + 6.0 * mu * mu * sa[2]
                  - 4.0 * mu * mu * mu * sa[1] + mu * mu * mu * mu * nv;
        double sg3 = sigma * sigma * sigma;
        double skew = (M3 / sg3) / nn;
        double kurt = (M4 / (sg3 * sigma)) / nn - 3.0;
        double valid = (nv >= 10.0) ? 1.0 : 0.0;

        float* o = out + b * 25;
        o[0] = (float)(mu * valid);
        o[1] = (float)(sigma * valid);
        o[2] = (float)(skew * valid);
        o[3] = (float)(kurt * valid);
        o[4] = (float)(ent * valid);
        for (int f = 0; f < 8; f++) o[5 + f] = (float)(sa[5 + f] / nn);
        for (int k = 0; k < 6; k++) o[13 + k] = (float)(sa[13 + k] / nn);
        for (int ax = 0; ax < 3; ax++) {
            double s = sa[19 + 3 * ax];
            double ss = s > 1.0 ? s : 1.0;
            double ok = (s >= 4.0) ? 1.0 : 0.0;
            o[19 + 2 * ax]     = (float)((sa[20 + 3 * ax] / ss) * ok);
            o[19 + 2 * ax + 1] = (float)((sa[21 + 3 * ax] / ss) * ok);
        }
    }
}

extern "C" void kernel_launch(void* const* d_in, const int* in_sizes, int n_in,
                              void* d_out, int out_size) {
    const float* x  = (const float*)d_in[0];
    const float* m  = (const float*)d_in[1];
    const float* gf = (const float*)d_in[2];

    dim3 grid(WW / TXX, HH / TYV, BB * 4);  // (5, 10, 16) = 800 CTAs
    dim3 blk(TXX, 8);
    fused_kernel<<<grid, blk>>>(x, m, gf);

    finalize_kernel<<<BB, 32>>>((float*)d_out);
}

// round 17
// speedup vs baseline: 1.1709x; 1.0908x over previous
#include <cuda_runtime.h>
#include <math.h>

#define BB 4
#define DD 96
#define HH 160
#define WW 160
#define HW (HH*WW)
#define NSCAL 28
#define NACC  78

// Global accumulators (double). Zero-initialized at module load;
// finalize_kernel re-zeroes after reading, so every subsequent
// launch/replay starts from zero. No zero_kernel needed.
__device__ double g_acc[BB][80];

typedef unsigned long long u64t;
__device__ __forceinline__ u64t pack2(float lo, float hi) {
    u64t r; asm("mov.b64 %0,{%1,%2};" : "=l"(r) : "f"(lo), "f"(hi)); return r;
}
__device__ __forceinline__ void unpack2(float& lo, float& hi, u64t v) {
    asm("mov.b64 {%0,%1},%2;" : "=f"(lo), "=f"(hi) : "l"(v));
}
__device__ __forceinline__ void fma2(u64t& d, u64t a, u64t b) {
    asm("fma.rn.f32x2 %0,%1,%2,%0;" : "+l"(d) : "l"(a), "l"(b));
}

// ============================================================
// Fused kernel (R15/R16 structure, byte-identical loop).
// ============================================================
#define TXX 32
#define TYV 16            // voxel rows per tile
#define HR  (TYV + 2)     // 18 halo rows
#define HC  (TXX + 2)     // 34 halo cols
#define ANL (HR * HC)     // 612
#define ZCH 24
#define HPITCH 260        // u8 row pitch (256 threads + 4 pad, /4 aligned)

__global__ __launch_bounds__(256, 3)
void fused_kernel(const float* __restrict__ X, const float* __restrict__ M,
                  const float* __restrict__ GF) {
    __shared__ float xsh[3][HR][HC];
    __shared__ float msk[3][HR][HC];
    __shared__ float2 aux[2][HR][HC];            // (t, s)
    __shared__ unsigned char h8[50 * HPITCH];    // per-thread histogram
    __shared__ float red[NSCAL][8];
    __shared__ float wsm[48];                    // w[8][5] + cf[8]

    const int tx = threadIdx.x, ty = threadIdx.y;     // ty in 0..7
    const int tid = ty * TXX + tx;
    const int warp = tid >> 5, lane = tid & 31;
    const int x0 = blockIdx.x * TXX, y0 = blockIdx.y * TYV;
    const int b = blockIdx.z >> 2;
    const int zs = (blockIdx.z & 3) * ZCH;   // multiple of 24 -> %3==0, even
    const float* Xb = X + (size_t)b * DD * HW;
    const float* Mb = M + (size_t)b * DD * HW;
    const float A = 0.13533528323661270f;  // exp(-2)

    // zero per-thread histogram (u32 strided)
    {
        unsigned* h32 = (unsigned*)h8;
        #pragma unroll
        for (int i = tid; i < 50 * HPITCH / 4; i += 256) h32[i] = 0u;
    }

    // derive weights (threads 0..7, one filter each):
    // F[dz][j] = gz[dz]*u[j] - c, gz=[a,1,a] => u[j]=(F1-F0)/(1-a)
    // conv = sum_sym ubar_k * tsym_k - cf*box ; u symmetric (u[j]==u[8-j])
    if (tid < 8) {
        float u[9], cacc = 0.0f;
        #pragma unroll
        for (int j = 0; j < 9; j++) {
            float F1 = GF[tid * 27 + 9 + j];
            float F0 = GF[tid * 27 + j];
            u[j] = (F1 - F0) * (1.0f / (1.0f - A));
            cacc += (u[j] - F1);
        }
        wsm[40 + tid] = cacc * (1.0f / 9.0f);
        wsm[tid * 5 + 0] = (u[0] + u[8]) * 0.5f;
        wsm[tid * 5 + 1] = (u[1] + u[7]) * 0.5f;
        wsm[tid * 5 + 2] = (u[2] + u[6]) * 0.5f;
        wsm[tid * 5 + 3] = (u[3] + u[5]) * 0.5f;
        wsm[tid * 5 + 4] = u[4];
    }

    // halo-load slots (3 segments, z-invariant)
    int loff[3]; bool lval[3];
    #pragma unroll
    for (int s = 0; s < 3; s++) {
        int i = tid + s * 256;
        bool ok = (i < ANL);
        int ry = ok ? i / HC : 0, rx = ok ? i % HC : 0;
        int gy = y0 + ry - 1, gx = x0 + rx - 1;
        lval[s] = ok && gy >= 0 && gy < HH && gx >= 0 && gx < WW;
        loff[s] = gy * WW + gx;
    }

    float xmR[3], xcR[3];

    // preload: x(zs-1)->xsh[2] (mask(zs-1) never read, not stored),
    // plane zs -> slot 0, zs+1 -> slot 1; aux(zs) -> slot 0.
    #pragma unroll
    for (int s = 0; s < 3; s++) {
        int i = tid + s * 256;
        if (i < ANL) {
            float xv_m = 0, xv_0 = 0, mv_0 = 0, xv_p = 0, mv_p = 0;
            if (lval[s]) {
                if (zs > 0) xv_m = __ldg(Xb + (size_t)(zs - 1) * HW + loff[s]);
                xv_0 = __ldg(Xb + (size_t)zs * HW + loff[s]);
                mv_0 = __ldg(Mb + (size_t)zs * HW + loff[s]);
                xv_p = __ldg(Xb + (size_t)(zs + 1) * HW + loff[s]);
                mv_p = __ldg(Mb + (size_t)(zs + 1) * HW + loff[s]);
            }
            (&xsh[2][0][0])[i] = xv_m;
            (&xsh[0][0][0])[i] = xv_0;  (&msk[0][0][0])[i] = mv_0;
            (&xsh[1][0][0])[i] = xv_p;  (&msk[1][0][0])[i] = mv_p;
            float mp2 = xv_m + xv_p;
            (&aux[0][0][0])[i] = make_float2(fmaf(A, mp2, xv_0), mp2 + xv_0);
            xmR[s] = xv_0;
            xcR[s] = xv_p;
        }
    }

    const u64t ABSM = 0x7FFFFFFF7FFFFFFFull;
    u64t gab2[4] = {0ull, 0ull, 0ull, 0ull};
    float n = 0, m1 = 0, m2 = 0, m3 = 0, m4 = 0;
    float lbp[6] = {0, 0, 0, 0, 0, 0};
    float gs[3] = {0, 0, 0}, gc[3] = {0, 0, 0}, gh[3] = {0, 0, 0};

    const int vy0 = 2 * ty + 1, vy1 = 2 * ty + 2, txc = tx + 1;

    __syncthreads();   // hist zero + weights + preload visible

    // packed weights: pair filters (2p, 2p+1)
    u64t w2[20], cf2[4];
    #pragma unroll
    for (int p = 0; p < 4; p++) {
        #pragma unroll
        for (int k = 0; k < 5; k++)
            w2[p * 5 + k] = pack2(wsm[(2 * p) * 5 + k], wsm[(2 * p + 1) * 5 + k]);
        cf2[p] = pack2(-wsm[40 + 2 * p], -wsm[40 + 2 * p + 1]);
    }

    // center-column register rotation state (c, xdn, mc per voxel)
    float cc0 = xsh[0][vy0][txc], cc1 = xsh[0][vy1][txc];
    float cd0 = xsh[2][vy0][txc], cd1 = xsh[2][vy1][txc];
    float cm0 = msk[0][vy0][txc], cm1 = msk[0][vy1][txc];

    // 3-slot ring indices: read q1,q2; write sw. zs%3==0.
    int q1 = 0, q2 = 1, sw = 2;
    int az = 0;

    for (int z = zs; z < zs + ZCH; z++) {
        // issue LDGs for plane z+2 early
        float xn[3] = {0, 0, 0}, mn[3] = {0, 0, 0};
        {
            int zq = z + 2;
            if (zq < DD) {
                const float* Px = Xb + (size_t)zq * HW;
                const float* Pm = Mb + (size_t)zq * HW;
                #pragma unroll
                for (int s = 0; s < 3; s++)
                    if (lval[s]) { xn[s] = __ldg(Px + loff[s]); mn[s] = __ldg(Pm + loff[s]); }
            }
        }

        // ---- aux window: 4 rows x 3 cols (12 LDS.64) covers both voxels ----
        float t[4][3], rowS[4];
        #pragma unroll
        for (int r = 0; r < 4; r++) {
            float2 a0 = aux[az][2 * ty + r][tx    ];
            float2 a1 = aux[az][2 * ty + r][tx + 1];
            float2 a2 = aux[az][2 * ty + r][tx + 2];
            t[r][0] = a0.x; t[r][1] = a1.x; t[r][2] = a2.x;
            rowS[r] = a0.y + a1.y + a2.y;
        }

        // ---- raw reads (split x / m); center column from registers ----
        float xv0 = xsh[q1][vy0 - 1][txc];
        float xv1 = cc0;
        float xv2 = cc1;
        float xv3 = xsh[q1][vy1 + 1][txc];
        float xxm0 = xsh[q1][vy0][tx], xxp0 = xsh[q1][vy0][tx + 2];
        float xxm1 = xsh[q1][vy1][tx], xxp1 = xsh[q1][vy1][tx + 2];
        float xup0 = xsh[q2][vy0][txc], xup1 = xsh[q2][vy1][txc];
        float xdn0 = cd0, xdn1 = cd1;
        float mc0 = cm0, mc1 = cm1;
        float myp1 = msk[q1][vy1 + 1][txc];
        float mxp0 = msk[q1][vy0][tx + 2], mxp1 = msk[q1][vy1][tx + 2];
        float mzp0 = msk[q2][vy0][txc], mzp1 = msk[q2][vy1][txc];

        #define DO_VOXEL(R, CC, MC, XUP, XDN, XYP, XYM, XXP, XXM, MZP, MYP, MXP)          \
        {                                                                                  \
            float C  = t[R][0] + t[R + 2][2];                                              \
            float CA = t[R][2] + t[R + 2][0];                                              \
            float Ey = t[R][1] + t[R + 2][1];                                              \
            float Ex = t[R + 1][0] + t[R + 1][2];                                          \
            float ct = t[R + 1][1];                                                        \
            float box = rowS[R] + rowS[R + 1] + rowS[R + 2];                               \
            u64t T0 = pack2(C, C),  T1 = pack2(Ey, Ey), T2 = pack2(CA, CA);                \
            u64t T3 = pack2(Ex, Ex), T4 = pack2(ct, ct), BX = pack2(box, box);             \
            u64t mcp = pack2(MC, MC);                                                      \
            _Pragma("unroll")                                                              \
            for (int p = 0; p < 4; p++) {                                                  \
                u64t acc = 0ull;                                                           \
                fma2(acc, w2[p * 5 + 0], T0);                                              \
                fma2(acc, w2[p * 5 + 1], T1);                                              \
                fma2(acc, w2[p * 5 + 2], T2);                                              \
                fma2(acc, w2[p * 5 + 3], T3);                                              \
                fma2(acc, w2[p * 5 + 4], T4);                                              \
                fma2(acc, cf2[p], BX);                                                     \
                acc &= ABSM;                                                               \
                fma2(gab2[p], acc, mcp);                                                   \
            }                                                                              \
            float c2 = CC * CC;                                                            \
            n += MC;                                                                       \
            m1 = fmaf(MC, CC, m1);                                                         \
            m2 = fmaf(MC, c2, m2);                                                         \
            float mcc = MC * CC;                                                           \
            m3 = fmaf(mcc, c2, m3);                                                        \
            m4 = fmaf(MC * c2, c2, m4);                                                    \
            if (MC > 0.5f && CC >= -1.0f && CC <= 1.0f) {                                  \
                int bi = (int)floorf(__fmul_rn(__fadd_rn(CC, 1.0f), 25.0f));               \
                bi = min(max(bi, 0), 49);                                                  \
                h8[bi * HPITCH + tid] += 1;                                                \
            }                                                                              \
            bool mb = MC > 0.5f;                                                           \
            if (mb) {                                                                      \
                lbp[0] += (CC - XUP > 0.0f) ? 1.0f : 0.0f;                                 \
                lbp[1] += (CC - XDN > 0.0f) ? 1.0f : 0.0f;                                 \
                lbp[2] += (CC - XYP > 0.0f) ? 1.0f : 0.0f;                                 \
                lbp[3] += (CC - XYM > 0.0f) ? 1.0f : 0.0f;                                 \
                lbp[4] += (CC - XXP > 0.0f) ? 1.0f : 0.0f;                                 \
                lbp[5] += (CC - XXM > 0.0f) ? 1.0f : 0.0f;                                 \
            }                                                                              \
            {                                                                              \
                float mp = (mb && MZP > 0.5f) ? 1.0f : 0.0f;                               \
                float d = CC - XUP, dd = d * d;                                            \
                gs[0] += mp;                                                               \
                gc[0] = fmaf(mp, dd, gc[0]);                                               \
                gh[0] = fmaf(mp, __fdividef(1.0f, 1.0f + dd), gh[0]);                      \
            }                                                                              \
            {                                                                              \
                float mp = (mb && MYP > 0.5f) ? 1.0f : 0.0f;                               \
                float d = CC - XYP, dd = d * d;                                            \
                gs[1] += mp;                                                               \
                gc[1] = fmaf(mp, dd, gc[1]);                                               \
                gh[1] = fmaf(mp, __fdividef(1.0f, 1.0f + dd), gh[1]);                      \
            }                                                                              \
            {                                                                              \
                float mp = (mb && MXP > 0.5f) ? 1.0f : 0.0f;                               \
                float d = CC - XXP, dd = d * d;                                            \
                gs[2] += mp;                                                               \
                gc[2] = fmaf(mp, dd, gc[2]);                                               \
                gh[2] = fmaf(mp, __fdividef(1.0f, 1.0f + dd), gh[2]);                      \
            }                                                                              \
        }

        DO_VOXEL(0, xv1, mc0, xup0, xdn0, xv2, xv0, xxp0, xxm0, mzp0, mc1,  mxp0)
        DO_VOXEL(1, xv2, mc1, xup1, xdn1, xv3, xv1, xxp1, xxm1, mzp1, myp1, mxp1)
        #undef DO_VOXEL

        // rotate center-column registers
        cd0 = cc0; cd1 = cc1;
        cc0 = xup0; cc1 = xup1;
        cm0 = mzp0; cm1 = mzp1;

        __syncthreads();   // all reads of current plane done before staging

        // ---- stage: aux(z+1) from register history; raw(z+2) -> slot sw ----
        {
            float* bx = &xsh[sw][0][0];
            float* bm = &msk[sw][0][0];
            float2* ba = &aux[az ^ 1][0][0];
            #pragma unroll
            for (int s = 0; s < 3; s++) {
                int i = tid + s * 256;
                if (s < 2 || i < ANL) {
                    float mp2 = xmR[s] + xn[s];
                    ba[i] = make_float2(fmaf(A, mp2, xcR[s]), mp2 + xcR[s]);
                    bx[i] = xn[s];
                    bm[i] = mn[s];
                    xmR[s] = xcR[s]; xcR[s] = xn[s];
                }
            }
        }
        __syncthreads();   // staging visible before next-plane reads

        // rotate ring indices
        int tq = q1; q1 = q2; q2 = sw; sw = tq;
        az ^= 1;
    }

    // ---- block reduction of 28 scalars ----
    float gabf[8];
    unpack2(gabf[0], gabf[1], gab2[0]);
    unpack2(gabf[2], gabf[3], gab2[1]);
    unpack2(gabf[4], gabf[5], gab2[2]);
    unpack2(gabf[6], gabf[7], gab2[3]);

    float vals[NSCAL];
    vals[0] = n; vals[1] = m1; vals[2] = m2; vals[3] = m3; vals[4] = m4;
    #pragma unroll
    for (int f = 0; f < 8; f++) vals[5 + f] = gabf[f];
    #pragma unroll
    for (int k = 0; k < 6; k++) vals[13 + k] = lbp[k];
    #pragma unroll
    for (int a = 0; a < 3; a++) {
        vals[19 + 3 * a] = gs[a];
        vals[20 + 3 * a] = gc[a];
        vals[21 + 3 * a] = gh[a];
    }

    #pragma unroll
    for (int k = 0; k < NSCAL; k++) {
        float v = vals[k];
        #pragma unroll
        for (int o = 16; o > 0; o >>= 1) v += __shfl_down_sync(0xffffffffu, v, o);
        if (lane == 0) red[k][warp] = v;
    }
    __syncthreads();

    if (tid < NSCAL) {
        double acc = 0.0;
        #pragma unroll
        for (int w = 0; w < 8; w++) acc += (double)red[tid][w];
        atomicAdd(&g_acc[b][tid], acc);
    }

    // ---- histogram reduction: warp w handles bins w, w+8, ...
    // 256 u8 counters per bin = 64 u32; lane sums 2 u32 via dp4a. ----
    for (int bbin = warp; bbin < 50; bbin += 8) {
        const unsigned* p = (const unsigned*)(h8 + bbin * HPITCH);
        unsigned s = 0;
        s = __dp4a(p[lane * 2 + 0], 0x01010101u, s);
        s = __dp4a(p[lane * 2 + 1], 0x01010101u, s);
        #pragma unroll
        for (int o = 16; o > 0; o >>= 1) s += __shfl_down_sync(0xffffffffu, s, o);
        if (lane == 0) atomicAdd(&g_acc[b][NSCAL + bbin], (double)s);
    }
}

// ============================================================
// Finalize: one warp per batch. Entropy computed in FLOAT
// (logf/MUFU — reference is f32 anyway); only the cancellation-
// sensitive moment tail stays double. Re-zeroes g_acc after
// reading so the next launch/replay starts clean.
// ============================================================
__global__ void finalize_kernel(float* __restrict__ out) {
    const int b = blockIdx.x;
    const int lane = threadIdx.x;
    double* a = g_acc[b];

    // load all 80 slots (<=3 per lane), then re-zero
    double v0 = a[lane];
    double v1 = (lane + 32 < 80) ? a[lane + 32] : 0.0;
    double v2 = (lane + 64 < 80) ? a[lane + 64] : 0.0;
    __syncwarp();
    a[lane] = 0.0;
    if (lane + 32 < 80) a[lane + 32] = 0.0;
    if (lane + 64 < 80) a[lane + 64] = 0.0;

    __shared__ double sa[80];
    sa[lane] = v0;
    if (lane + 32 < 80) sa[lane + 32] = v1;
    if (lane + 64 < 80) sa[lane + 64] = v2;
    __syncwarp();

    // total histogram mass (double adds are cheap DADD)
    double tot = 0.0;
    for (int k = lane; k < 50; k += 32) tot += sa[NSCAL + k];
    #pragma unroll
    for (int o = 16; o > 0; o >>= 1) tot += __shfl_down_sync(0xffffffffu, tot, o);
    tot = __shfl_sync(0xffffffffu, tot, 0);
    tot += 1e-8;

    // entropy in float: one double division, then MUFU logf
    float inv_tot = (float)(1.0 / tot);
    float entf = 0.0f;
    for (int k = lane; k < 50; k += 32) {
        float p = (float)sa[NSCAL + k] * inv_tot;
        entf -= p * logf(p + 1e-8f);
    }
    #pragma unroll
    for (int o = 16; o > 0; o >>= 1) entf += __shfl_down_sync(0xffffffffu, entf, o);

    if (lane == 0) {
        double nv = sa[0];
        double nn = nv > 1.0 ? nv : 1.0;
        double inv_nn = 1.0 / nn;
        double mu = sa[1] * inv_nn;
        double M2 = sa[2] - 2.0 * mu * sa[1] + mu * mu * nv;
        double nm1 = (nv - 1.0) > 1.0 ? (nv - 1.0) : 1.0;
        double var = M2 / nm1;
        double sigma = sqrt(var) + 1e-8;
        double M3 = sa[3] - 3.0 * mu * sa[2] + 3.0 * mu * mu * sa[1] - mu * mu * mu * nv;
        double M4 = sa[4] - 4.0 * mu * sa[3] + 6.0 * mu * mu * sa[2]
                  - 4.0 * mu * mu * mu * sa[1] + mu * mu * mu * mu * nv;
        double sg3 = sigma * sigma * sigma;
        double skew = (M3 / sg3) * inv_nn;
        double kurt = (M4 / (sg3 * sigma)) * inv_nn - 3.0;
        double valid = (nv >= 10.0) ? 1.0 : 0.0;

        float* o = out + b * 25;
        o[0] = (float)(mu * valid);
        o[1] = (float)(sigma * valid);
        o[2] = (float)(skew * valid);
        o[3] = (float)(kurt * valid);
        o[4] = (float)((double)entf * valid);
        for (int f = 0; f < 8; f++) o[5 + f] = (float)(sa[5 + f] * inv_nn);
        for (int k = 0; k < 6; k++) o[13 + k] = (float)(sa[13 + k] * inv_nn);
        for (int ax = 0; ax < 3; ax++) {
            double s = sa[19 + 3 * ax];
            double iss = 1.0 / (s > 1.0 ? s : 1.0);
            double ok = (s >= 4.0) ? 1.0 : 0.0;
            o[19 + 2 * ax]     = (float)((sa[20 + 3 * ax] * iss) * ok);
            o[19 + 2 * ax + 1] = (float)((sa[21 + 3 * ax] * iss) * ok);
        }
    }
}

extern "C" void kernel_launch(void* const* d_in, const int* in_sizes, int n_in,
                              void* d_out, int out_size) {
    const float* x  = (const float*)d_in[0];
    const float* m  = (const float*)d_in[1];
    const float* gf = (const float*)d_in[2];

    dim3 grid(WW / TXX, HH / TYV, BB * 4);  // (5, 10, 16) = 800 CTAs
    dim3 blk(TXX, 8);
    fused_kernel<<<grid, blk>>>(x, m, gf);

    finalize_kernel<<<BB, 32>>>((float*)d_out);
}